// round 14
// baseline (speedup 1.0000x reference)
#include <cuda_runtime.h>
#include <cstdint>

// Problem constants (fixed by the reference)
#define IN_C   128
#define HID_C  128
#define OUT_C  64
#define K_CL   32
#define MAXN   131072   // N = 100000 actual

// ---------------- scratch (device globals; no allocation allowed) ----------------
__device__ float g_deg [MAXN];
__device__ float g_dinv[MAXN];
__device__ float g_xw1 [MAXN * HID_C];   // x @ W1
__device__ float g_acc [MAXN * HID_C];   // aggregation accumulator / h after relu
__device__ float g_hw2 [MAXN * OUT_C];   // h @ W2

// ---------------- small utility kernels ----------------
__global__ void k_init_deg(int N) {
    int i = blockIdx.x * blockDim.x + threadIdx.x;
    if (i < N) g_deg[i] = 1.0f;   // self-loop
}

__global__ void k_deg(const int* __restrict__ dst, int E, int N) {
    int stride = gridDim.x * blockDim.x;
    for (int e = blockIdx.x * blockDim.x + threadIdx.x; e < E; e += stride) {
        int d = dst[e];
        if ((unsigned)d < (unsigned)N) atomicAdd(&g_deg[d], 1.0f);
    }
}

__global__ void k_dinv(int N) {
    int i = blockIdx.x * blockDim.x + threadIdx.x;
    if (i < N) g_dinv[i] = rsqrtf(g_deg[i]);
}

__global__ void k_zero(float* __restrict__ p, int n4) {
    int stride = gridDim.x * blockDim.x;
    float4 zero = make_float4(0.f, 0.f, 0.f, 0.f);
    float4* p4 = reinterpret_cast<float4*>(p);
    for (int i = blockIdx.x * blockDim.x + threadIdx.x; i < n4; i += stride)
        p4[i] = zero;
}

// a := relu(a + b), a is [N, HID_C]
__global__ void k_bias_relu(float* __restrict__ a, const float* __restrict__ b, int N) {
    int stride = gridDim.x * blockDim.x;
    int total = N * HID_C;
    for (int i = blockIdx.x * blockDim.x + threadIdx.x; i < total; i += stride)
        a[i] = fmaxf(a[i] + b[i & (HID_C - 1)], 0.f);
}

// a := a + b, a is [N, OUT_C]
__global__ void k_bias(float* __restrict__ a, const float* __restrict__ b, int N) {
    int stride = gridDim.x * blockDim.x;
    int total = N * OUT_C;
    for (int i = blockIdx.x * blockDim.x + threadIdx.x; i < total; i += stride)
        a[i] = a[i] + b[i & (OUT_C - 1)];
}

// ---------------- SGEMM: C[M,BN] = A[M,128] * B[128,BN] ----------------
// BM=128, BK=8, 256 threads, thread tile 8 x (BN/16)
template <int BN>
__global__ __launch_bounds__(256) void k_sgemm(const float* __restrict__ A,
                                               const float* __restrict__ Bm,
                                               float* __restrict__ C, int M) {
    constexpr int BM = 128, BK = 8, TM = 8, TN = BN / 16;
    __shared__ __align__(16) float As[BK][BM];
    __shared__ __align__(16) float Bs[BK][BN];

    const int tid  = threadIdx.x;
    const int row0 = blockIdx.x * BM;
    const int tr   = tid / 16;       // 0..15
    const int tc   = tid % 16;       // 0..15

    float acc[TM][TN];
#pragma unroll
    for (int i = 0; i < TM; i++)
#pragma unroll
        for (int j = 0; j < TN; j++) acc[i][j] = 0.f;

    const int a_row = tid >> 1;           // 0..127
    const int a_k   = (tid & 1) * 4;      // 0 or 4

#pragma unroll 1
    for (int kb = 0; kb < 16; kb++) {
        const int k0 = kb * BK;
        float4 av = make_float4(0.f, 0.f, 0.f, 0.f);
        if (row0 + a_row < M)
            av = *reinterpret_cast<const float4*>(A + (size_t)(row0 + a_row) * 128 + k0 + a_k);
        As[a_k + 0][a_row] = av.x;
        As[a_k + 1][a_row] = av.y;
        As[a_k + 2][a_row] = av.z;
        As[a_k + 3][a_row] = av.w;
        if (BN == 128) {
            const int br = tid >> 5, bc = (tid & 31) * 4;
            *reinterpret_cast<float4*>(&Bs[br][bc]) =
                *reinterpret_cast<const float4*>(Bm + (size_t)(k0 + br) * BN + bc);
        } else {
            const int br = tid >> 5, bc = (tid & 31) * 2;
            *reinterpret_cast<float2*>(&Bs[br][bc]) =
                *reinterpret_cast<const float2*>(Bm + (size_t)(k0 + br) * BN + bc);
        }
        __syncthreads();

#pragma unroll
        for (int k = 0; k < BK; k++) {
            float ra[TM], rb[TN];
            *reinterpret_cast<float4*>(&ra[0]) = *reinterpret_cast<const float4*>(&As[k][tr * TM]);
            *reinterpret_cast<float4*>(&ra[4]) = *reinterpret_cast<const float4*>(&As[k][tr * TM + 4]);
#pragma unroll
            for (int j = 0; j < TN; j += 4)
                *reinterpret_cast<float4*>(&rb[j]) = *reinterpret_cast<const float4*>(&Bs[k][tc * TN + j]);
#pragma unroll
            for (int i = 0; i < TM; i++)
#pragma unroll
                for (int j = 0; j < TN; j++) acc[i][j] += ra[i] * rb[j];
        }
        __syncthreads();
    }

#pragma unroll
    for (int i = 0; i < TM; i++) {
        int r = row0 + tr * TM + i;
        if (r < M) {
#pragma unroll
            for (int j = 0; j < TN; j += 4) {
                float4 v = make_float4(acc[i][j], acc[i][j + 1], acc[i][j + 2], acc[i][j + 3]);
                *reinterpret_cast<float4*>(C + (size_t)r * BN + tc * TN + j) = v;
            }
        }
    }
}

// ---------------- edge aggregation (literal mirror of the reference) ----------------
// Edges e in [0,E): acc[dst[e]] += feat[src[e]] * dinv[src]*dinv[dst]
// Edges e in [E,E+N): self-loop, s=d=e-E (weight dinv^2).
// One thread handles one (edge, 4-float chunk).
template <int C>
__global__ void k_agg(const float* __restrict__ feat,
                      const int* __restrict__ src,
                      const int* __restrict__ dst,
                      float* __restrict__ acc, int E, int N) {
    const int CH4 = C / 4;
    const long long total = (long long)(E + N) * CH4;
    const long long stride = (long long)gridDim.x * blockDim.x;
    for (long long i = (long long)blockIdx.x * blockDim.x + threadIdx.x; i < total; i += stride) {
        const int e = (int)(i / CH4);
        const int c = (int)(i - (long long)e * CH4);
        int s, d;
        if (e < E) {
            s = src[e]; d = dst[e];
            if ((unsigned)s >= (unsigned)N) s = 0;   // graceful degradation on bad parse
            if ((unsigned)d >= (unsigned)N) d = 0;
        } else {
            s = d = e - E;
        }
        const float w = g_dinv[s] * g_dinv[d];
        const float4 v = *reinterpret_cast<const float4*>(feat + (size_t)s * C + c * 4);
        float* ar = acc + (size_t)d * C + c * 4;
        atomicAdd(ar + 0, v.x * w);
        atomicAdd(ar + 1, v.y * w);
        atomicAdd(ar + 2, v.z * w);
        atomicAdd(ar + 3, v.w * w);
    }
}

// ---------------- Student-t soft assignment ----------------
__global__ __launch_bounds__(256) void k_q(const float* __restrict__ z,
                                           const float* __restrict__ cluster,
                                           float* __restrict__ q, int N) {
    __shared__ float cl[K_CL * OUT_C];
    __shared__ float cc[K_CL];
    for (int i = threadIdx.x; i < K_CL * OUT_C; i += blockDim.x) cl[i] = cluster[i];
    __syncthreads();
    if (threadIdx.x < K_CL) {
        float s = 0.f;
#pragma unroll
        for (int j = 0; j < OUT_C; j++) { float c = cl[threadIdx.x * OUT_C + j]; s += c * c; }
        cc[threadIdx.x] = s;
    }
    __syncthreads();

    const int stride = gridDim.x * blockDim.x;
    for (int n = blockIdx.x * blockDim.x + threadIdx.x; n < N; n += stride) {
        float zr[OUT_C];
        const float4* zp = reinterpret_cast<const float4*>(z + (size_t)n * OUT_C);
#pragma unroll
        for (int i = 0; i < OUT_C / 4; i++) reinterpret_cast<float4*>(zr)[i] = zp[i];
        float zz = 0.f;
#pragma unroll
        for (int j = 0; j < OUT_C; j++) zz += zr[j] * zr[j];

        float qv[K_CL];
        float sum = 0.f;
#pragma unroll 4
        for (int k = 0; k < K_CL; k++) {
            float dot = 0.f;
#pragma unroll
            for (int j = 0; j < OUT_C; j++) dot += zr[j] * cl[k * OUT_C + j];
            float sq = fmaxf(zz + cc[k] - 2.f * dot, 0.f);
            float t  = 1.f + 0.5f * sq;       // V = 2
            float r  = rsqrtf(t);
            float v  = r * r * r;             // (1+sq/V)^{-(V+1)/2}
            qv[k] = v;
            sum += v;
        }
        float inv = 1.f / sum;
#pragma unroll
        for (int k = 0; k < K_CL; k++) q[(size_t)n * K_CL + k] = qv[k] * inv;
    }
}

// ---------------- launch ----------------
extern "C" void kernel_launch(void* const* d_in, const int* in_sizes, int n_in,
                              void* d_out, int out_size) {
    // N from out_size (z[N,64] + q[N,32] = 96 floats per node) — independent of in_sizes.
    int N = out_size / 96;
    if ((long long)N * 96 != (long long)out_size || N > MAXN) {
        int nb = out_size / (96 * 4);                 // bytes fallback
        if (nb > 0 && (long long)nb * 96 * 4 == (long long)out_size && nb <= MAXN) N = nb;
    }
    if (N > MAXN) N = MAXN;
    if (N <= 0) N = 100000;

    // Determine unit (1=elements, 4=bytes) via the W1 signature, which is
    // collision-free under BOTH conventions (16384 elems / 65536 bytes —
    // no other buffer matches either). x's own signature collides with
    // bytes-edge_index (12.8M), so W1 is the safe probe.
    int unit = 0;
    for (int i = 0; i < n_in && unit == 0; i++)
        if (in_sizes[i] == IN_C * HID_C) unit = 1;
    for (int i = 0; i < n_in && unit == 0; i++)
        if (in_sizes[i] == IN_C * HID_C * 4) unit = 4;
    if (unit == 0) unit = 1;

    // Bind x by its (now unambiguous) signature.
    int xi = -1;
    for (int i = 0; i < n_in && xi < 0; i++)
        if (in_sizes[i] == N * IN_C * unit) xi = i;
    if (xi < 0) xi = 0;

    const float* x = (const float*)d_in[xi];
    const float* W1 = nullptr; const float* b1 = nullptr;
    const float* W2 = nullptr; const float* b2 = nullptr;
    const float* cluster = nullptr;
    const int* ei = nullptr; int E = 0;
    bool used[16] = {false};
    if (xi >= 0 && xi < 16) used[xi] = true;

    for (int i = 0; i < n_in && i < 16; i++) {
        if (used[i]) continue;
        const int sz = in_sizes[i];
        if      (sz == IN_C * HID_C * unit && !W1)      { W1 = (const float*)d_in[i]; used[i] = true; }
        else if (sz == HID_C * OUT_C * unit && !W2)     { W2 = (const float*)d_in[i]; used[i] = true; }
        else if (sz == K_CL * OUT_C * unit && !cluster) { cluster = (const float*)d_in[i]; used[i] = true; }
        else if (sz == HID_C * unit && !b1)             { b1 = (const float*)d_in[i]; used[i] = true; }
        else if (sz == OUT_C * unit && !b2)             { b2 = (const float*)d_in[i]; used[i] = true; }
    }
    // edge_index = largest remaining buffer
    int best = -1;
    for (int i = 0; i < n_in && i < 16; i++)
        if (!used[i] && (best < 0 || in_sizes[i] > in_sizes[best])) best = i;
    if (best >= 0) { ei = (const int*)d_in[best]; E = in_sizes[best] / (2 * unit); }
    // positional fallback for anything unresolved
    if (!ei && n_in > 1)     { ei = (const int*)d_in[1]; E = in_sizes[1] / 2; }
    if (!W1 && n_in > 2)      W1      = (const float*)d_in[2];
    if (!b1 && n_in > 3)      b1      = (const float*)d_in[3];
    if (!W2 && n_in > 4)      W2      = (const float*)d_in[4];
    if (!b2 && n_in > 5)      b2      = (const float*)d_in[5];
    if (!cluster && n_in > 6) cluster = (const float*)d_in[6];

    const int* src = ei;
    const int* dst = ei + E;

    float* z = (float*)d_out;                      // [N, 64]
    float* q = (float*)d_out + (size_t)N * OUT_C;  // [N, 32]

    const int G1 = 148 * 8;     // elementwise grids
    const int G2 = 148 * 32;    // aggregation grids

    // degrees (with self-loop) -> dinv
    k_init_deg<<<(N + 255) / 256, 256>>>(N);
    k_deg<<<148 * 4, 256>>>(dst, E, N);
    k_dinv<<<(N + 255) / 256, 256>>>(N);

    // layer 1: xw1 = x @ W1 ; acc = Ahat * xw1 ; h = relu(acc + b1)
    k_sgemm<HID_C><<<(N + 127) / 128, 256>>>(x, W1, g_xw1, N);
    k_zero<<<G1, 256>>>(g_acc, N * (HID_C / 4));
    k_agg<HID_C><<<G2, 256>>>(g_xw1, src, dst, g_acc, E, N);
    k_bias_relu<<<G1, 256>>>(g_acc, b1, N);

    // layer 2: hw2 = h @ W2 ; z = Ahat * hw2 + b2
    k_sgemm<OUT_C><<<(N + 127) / 128, 256>>>(g_acc, W2, g_hw2, N);
    k_zero<<<G1, 256>>>(z, N * (OUT_C / 4));
    k_agg<OUT_C><<<G2, 256>>>(g_hw2, src, dst, z, E, N);
    k_bias<<<G1, 256>>>(z, b2, N);

    // Student-t soft assignment
    k_q<<<148 * 8, 256>>>(z, cluster, q, N);
}

// round 15
// speedup vs baseline: 4.3140x; 4.3140x over previous
#include <cuda_runtime.h>
#include <cstdint>

// Problem constants (fixed by the reference)
#define IN_C   128
#define HID_C  128
#define OUT_C  64
#define K_CL   32
#define MAXN   131072   // N = 100000 actual
#define MAXE   2097152  // E = 1.6M actual

// ---------------- scratch (device globals; no allocation allowed) ----------------
__device__ float g_dinv[MAXN];
__device__ int   g_cnt [MAXN];          // incoming-edge count (excl. self-loop)
__device__ int   g_cur [MAXN];          // scatter cursors
__device__ int   g_row [MAXN];          // CSR row starts (exclusive prefix of cnt)
__device__ int   g_csum[256];           // per-chunk sums for scan
__device__ int   g_coff[256];           // per-chunk offsets for scan
__device__ int   g_csr [MAXE];          // CSR: src indices bucketed by dst
__device__ float g_xw1 [MAXN * HID_C];  // x @ W1
__device__ float g_acc [MAXN * HID_C];  // h after gather+bias+relu
__device__ float g_hw2 [MAXN * OUT_C];  // h @ W2

// ---------------- CSR build ----------------
__global__ void k_zero_cc(int N) {
    int i = blockIdx.x * blockDim.x + threadIdx.x;
    if (i < N) { g_cnt[i] = 0; g_cur[i] = 0; }
}

__global__ void k_hist(const int* __restrict__ dst, int E, int N) {
    int stride = gridDim.x * blockDim.x;
    for (int e = blockIdx.x * blockDim.x + threadIdx.x; e < E; e += stride) {
        int d = dst[e];
        if ((unsigned)d < (unsigned)N) atomicAdd(&g_cnt[d], 1);
    }
}

__global__ void k_dinv(int N) {
    int i = blockIdx.x * blockDim.x + threadIdx.x;
    if (i < N) g_dinv[i] = rsqrtf(1.0f + (float)g_cnt[i]);   // +1 = self-loop
}

// scan step A: per-chunk (1024 elems) sums
__global__ void k_scan_a(int N) {
    __shared__ int sh[256];
    int b = blockIdx.x, t = threadIdx.x;
    int base = b * 1024 + t * 4;
    int s = 0;
#pragma unroll
    for (int k = 0; k < 4; k++) { int idx = base + k; if (idx < N) s += g_cnt[idx]; }
    sh[t] = s; __syncthreads();
    for (int d = 128; d > 0; d >>= 1) { if (t < d) sh[t] += sh[t + d]; __syncthreads(); }
    if (t == 0) g_csum[b] = sh[0];
}

// scan step B: serial exclusive scan of chunk sums (nchunk <= 128)
__global__ void k_scan_b(int nchunk) {
    if (blockIdx.x == 0 && threadIdx.x == 0) {
        int acc = 0;
        for (int i = 0; i < nchunk; i++) { g_coff[i] = acc; acc += g_csum[i]; }
    }
}

// scan step C: per-chunk exclusive scan + chunk offset -> row starts
__global__ void k_scan_c(int N) {
    __shared__ int sh[256];
    int b = blockIdx.x, t = threadIdx.x;
    int base = b * 1024 + t * 4;
    int v0 = 0, v1 = 0, v2 = 0, v3 = 0;
    if (base + 0 < N) v0 = g_cnt[base + 0];
    if (base + 1 < N) v1 = g_cnt[base + 1];
    if (base + 2 < N) v2 = g_cnt[base + 2];
    if (base + 3 < N) v3 = g_cnt[base + 3];
    sh[t] = v0 + v1 + v2 + v3; __syncthreads();
    // Hillis-Steele inclusive scan
    for (int d = 1; d < 256; d <<= 1) {
        int x = (t >= d) ? sh[t - d] : 0;
        __syncthreads();
        sh[t] += x;
        __syncthreads();
    }
    int excl = ((t > 0) ? sh[t - 1] : 0) + g_coff[b];
    if (base + 0 < N) g_row[base + 0] = excl; excl += v0;
    if (base + 1 < N) g_row[base + 1] = excl; excl += v1;
    if (base + 2 < N) g_row[base + 2] = excl; excl += v2;
    if (base + 3 < N) g_row[base + 3] = excl;
}

__global__ void k_scatter(const int* __restrict__ src, const int* __restrict__ dst,
                          int E, int N) {
    int stride = gridDim.x * blockDim.x;
    for (int e = blockIdx.x * blockDim.x + threadIdx.x; e < E; e += stride) {
        int d = dst[e];
        if ((unsigned)d >= (unsigned)N) continue;     // consistent with k_hist
        int s = src[e];
        if ((unsigned)s >= (unsigned)N) s = 0;
        int pos = atomicAdd(&g_cur[d], 1);
        g_csr[g_row[d] + pos] = s;
    }
}

// ---------------- SGEMM: C[M,BN] = A[M,128] * B[128,BN] ----------------
template <int BN>
__global__ __launch_bounds__(256) void k_sgemm(const float* __restrict__ A,
                                               const float* __restrict__ Bm,
                                               float* __restrict__ C, int M) {
    constexpr int BM = 128, BK = 8, TM = 8, TN = BN / 16;
    __shared__ __align__(16) float As[BK][BM];
    __shared__ __align__(16) float Bs[BK][BN];

    const int tid  = threadIdx.x;
    const int row0 = blockIdx.x * BM;
    const int tr   = tid / 16;
    const int tc   = tid % 16;

    float acc[TM][TN];
#pragma unroll
    for (int i = 0; i < TM; i++)
#pragma unroll
        for (int j = 0; j < TN; j++) acc[i][j] = 0.f;

    const int a_row = tid >> 1;
    const int a_k   = (tid & 1) * 4;

#pragma unroll 1
    for (int kb = 0; kb < 16; kb++) {
        const int k0 = kb * BK;
        float4 av = make_float4(0.f, 0.f, 0.f, 0.f);
        if (row0 + a_row < M)
            av = *reinterpret_cast<const float4*>(A + (size_t)(row0 + a_row) * 128 + k0 + a_k);
        As[a_k + 0][a_row] = av.x;
        As[a_k + 1][a_row] = av.y;
        As[a_k + 2][a_row] = av.z;
        As[a_k + 3][a_row] = av.w;
        if (BN == 128) {
            const int br = tid >> 5, bc = (tid & 31) * 4;
            *reinterpret_cast<float4*>(&Bs[br][bc]) =
                *reinterpret_cast<const float4*>(Bm + (size_t)(k0 + br) * BN + bc);
        } else {
            const int br = tid >> 5, bc = (tid & 31) * 2;
            *reinterpret_cast<float2*>(&Bs[br][bc]) =
                *reinterpret_cast<const float2*>(Bm + (size_t)(k0 + br) * BN + bc);
        }
        __syncthreads();

#pragma unroll
        for (int k = 0; k < BK; k++) {
            float ra[TM], rb[TN];
            *reinterpret_cast<float4*>(&ra[0]) = *reinterpret_cast<const float4*>(&As[k][tr * TM]);
            *reinterpret_cast<float4*>(&ra[4]) = *reinterpret_cast<const float4*>(&As[k][tr * TM + 4]);
#pragma unroll
            for (int j = 0; j < TN; j += 4)
                *reinterpret_cast<float4*>(&rb[j]) = *reinterpret_cast<const float4*>(&Bs[k][tc * TN + j]);
#pragma unroll
            for (int i = 0; i < TM; i++)
#pragma unroll
                for (int j = 0; j < TN; j++) acc[i][j] += ra[i] * rb[j];
        }
        __syncthreads();
    }

#pragma unroll
    for (int i = 0; i < TM; i++) {
        int r = row0 + tr * TM + i;
        if (r < M) {
#pragma unroll
            for (int j = 0; j < TN; j += 4) {
                float4 v = make_float4(acc[i][j], acc[i][j + 1], acc[i][j + 2], acc[i][j + 3]);
                *reinterpret_cast<float4*>(C + (size_t)r * BN + tc * TN + j) = v;
            }
        }
    }
}

// ---------------- pull-based aggregation (CSR gather; NO atomics) ----------------
// out[n] = sum_{s in in(n)} feat[s]*dinv[s]*dinv[n] + feat[n]*dinv[n]^2 + bias
// One warp per node; lane holds C/32 floats.
template <int C, bool RELU>
__global__ void k_gather(const float* __restrict__ feat, const float* __restrict__ bias,
                         float* __restrict__ out, int N) {
    const int lane  = threadIdx.x & 31;
    int warp        = (blockIdx.x * blockDim.x + threadIdx.x) >> 5;
    const int nwarp = (gridDim.x * blockDim.x) >> 5;

    for (int n = warp; n < N; n += nwarp) {
        const float di  = g_dinv[n];
        const int   beg = g_row[n];
        const int   deg = g_cnt[n];
        if (C == 128) {
            float4 a = *reinterpret_cast<const float4*>(feat + (size_t)n * C + lane * 4);
            const float w0 = di * di;
            a.x *= w0; a.y *= w0; a.z *= w0; a.w *= w0;
            for (int j = 0; j < deg; j++) {
                const int s = g_csr[beg + j];
                const float w = g_dinv[s] * di;
                float4 v = *reinterpret_cast<const float4*>(feat + (size_t)s * C + lane * 4);
                a.x = fmaf(v.x, w, a.x);
                a.y = fmaf(v.y, w, a.y);
                a.z = fmaf(v.z, w, a.z);
                a.w = fmaf(v.w, w, a.w);
            }
            float4 b = *reinterpret_cast<const float4*>(bias + lane * 4);
            a.x += b.x; a.y += b.y; a.z += b.z; a.w += b.w;
            if (RELU) {
                a.x = fmaxf(a.x, 0.f); a.y = fmaxf(a.y, 0.f);
                a.z = fmaxf(a.z, 0.f); a.w = fmaxf(a.w, 0.f);
            }
            *reinterpret_cast<float4*>(out + (size_t)n * C + lane * 4) = a;
        } else {
            float2 a = *reinterpret_cast<const float2*>(feat + (size_t)n * C + lane * 2);
            const float w0 = di * di;
            a.x *= w0; a.y *= w0;
            for (int j = 0; j < deg; j++) {
                const int s = g_csr[beg + j];
                const float w = g_dinv[s] * di;
                float2 v = *reinterpret_cast<const float2*>(feat + (size_t)s * C + lane * 2);
                a.x = fmaf(v.x, w, a.x);
                a.y = fmaf(v.y, w, a.y);
            }
            float2 b = *reinterpret_cast<const float2*>(bias + lane * 2);
            a.x += b.x; a.y += b.y;
            if (RELU) { a.x = fmaxf(a.x, 0.f); a.y = fmaxf(a.y, 0.f); }
            *reinterpret_cast<float2*>(out + (size_t)n * C + lane * 2) = a;
        }
    }
}

// ---------------- Student-t soft assignment ----------------
__global__ __launch_bounds__(256) void k_q(const float* __restrict__ z,
                                           const float* __restrict__ cluster,
                                           float* __restrict__ q, int N) {
    __shared__ float cl[K_CL * OUT_C];
    __shared__ float cc[K_CL];
    for (int i = threadIdx.x; i < K_CL * OUT_C; i += blockDim.x) cl[i] = cluster[i];
    __syncthreads();
    if (threadIdx.x < K_CL) {
        float s = 0.f;
#pragma unroll
        for (int j = 0; j < OUT_C; j++) { float c = cl[threadIdx.x * OUT_C + j]; s += c * c; }
        cc[threadIdx.x] = s;
    }
    __syncthreads();

    const int stride = gridDim.x * blockDim.x;
    for (int n = blockIdx.x * blockDim.x + threadIdx.x; n < N; n += stride) {
        float zr[OUT_C];
        const float4* zp = reinterpret_cast<const float4*>(z + (size_t)n * OUT_C);
#pragma unroll
        for (int i = 0; i < OUT_C / 4; i++) reinterpret_cast<float4*>(zr)[i] = zp[i];
        float zz = 0.f;
#pragma unroll
        for (int j = 0; j < OUT_C; j++) zz += zr[j] * zr[j];

        float qv[K_CL];
        float sum = 0.f;
#pragma unroll 4
        for (int k = 0; k < K_CL; k++) {
            float dot = 0.f;
#pragma unroll
            for (int j = 0; j < OUT_C; j++) dot += zr[j] * cl[k * OUT_C + j];
            float sq = fmaxf(zz + cc[k] - 2.f * dot, 0.f);
            float t  = 1.f + 0.5f * sq;       // V = 2
            float r  = rsqrtf(t);
            float v  = r * r * r;             // (1+sq/V)^{-(V+1)/2}
            qv[k] = v;
            sum += v;
        }
        float inv = 1.f / sum;
#pragma unroll
        for (int k = 0; k < K_CL; k++) q[(size_t)n * K_CL + k] = qv[k] * inv;
    }
}

// ---------------- launch ----------------
extern "C" void kernel_launch(void* const* d_in, const int* in_sizes, int n_in,
                              void* d_out, int out_size) {
    // N from out_size (z[N,64] + q[N,32] = 96 floats per node).
    int N = out_size / 96;
    if ((long long)N * 96 != (long long)out_size || N > MAXN) {
        int nb = out_size / (96 * 4);
        if (nb > 0 && (long long)nb * 96 * 4 == (long long)out_size && nb <= MAXN) N = nb;
    }
    if (N > MAXN) N = MAXN;
    if (N <= 0) N = 100000;

    // unit via W1 signature (collision-free both conventions)
    int unit = 0;
    for (int i = 0; i < n_in && unit == 0; i++)
        if (in_sizes[i] == IN_C * HID_C) unit = 1;
    for (int i = 0; i < n_in && unit == 0; i++)
        if (in_sizes[i] == IN_C * HID_C * 4) unit = 4;
    if (unit == 0) unit = 1;

    int xi = -1;
    for (int i = 0; i < n_in && xi < 0; i++)
        if (in_sizes[i] == N * IN_C * unit) xi = i;
    if (xi < 0) xi = 0;

    const float* x = (const float*)d_in[xi];
    const float* W1 = nullptr; const float* b1 = nullptr;
    const float* W2 = nullptr; const float* b2 = nullptr;
    const float* cluster = nullptr;
    const int* ei = nullptr; int E = 0;
    bool used[16] = {false};
    if (xi >= 0 && xi < 16) used[xi] = true;

    for (int i = 0; i < n_in && i < 16; i++) {
        if (used[i]) continue;
        const int sz = in_sizes[i];
        if      (sz == IN_C * HID_C * unit && !W1)      { W1 = (const float*)d_in[i]; used[i] = true; }
        else if (sz == HID_C * OUT_C * unit && !W2)     { W2 = (const float*)d_in[i]; used[i] = true; }
        else if (sz == K_CL * OUT_C * unit && !cluster) { cluster = (const float*)d_in[i]; used[i] = true; }
        else if (sz == HID_C * unit && !b1)             { b1 = (const float*)d_in[i]; used[i] = true; }
        else if (sz == OUT_C * unit && !b2)             { b2 = (const float*)d_in[i]; used[i] = true; }
    }
    int best = -1;
    for (int i = 0; i < n_in && i < 16; i++)
        if (!used[i] && (best < 0 || in_sizes[i] > in_sizes[best])) best = i;
    if (best >= 0) { ei = (const int*)d_in[best]; E = in_sizes[best] / (2 * unit); }
    if (!ei && n_in > 1)     { ei = (const int*)d_in[1]; E = in_sizes[1] / 2; }
    if (!W1 && n_in > 2)      W1      = (const float*)d_in[2];
    if (!b1 && n_in > 3)      b1      = (const float*)d_in[3];
    if (!W2 && n_in > 4)      W2      = (const float*)d_in[4];
    if (!b2 && n_in > 5)      b2      = (const float*)d_in[5];
    if (!cluster && n_in > 6) cluster = (const float*)d_in[6];
    if (E > MAXE) E = MAXE;

    const int* src = ei;
    const int* dst = ei + E;

    float* z = (float*)d_out;                      // [N, 64]
    float* q = (float*)d_out + (size_t)N * OUT_C;  // [N, 32]

    const int nchunk = (N + 1023) / 1024;
    const int GE = 148 * 4;     // edge-indexed grids
    const int GW = 148 * 16;    // warp-per-node gather grids

    // CSR build: hist -> dinv -> scan(row starts) -> scatter
    k_zero_cc<<<(N + 255) / 256, 256>>>(N);
    k_hist<<<GE, 256>>>(dst, E, N);
    k_dinv<<<(N + 255) / 256, 256>>>(N);
    k_scan_a<<<nchunk, 256>>>(N);
    k_scan_b<<<1, 32>>>(nchunk);
    k_scan_c<<<nchunk, 256>>>(N);
    k_scatter<<<GE, 256>>>(src, dst, E, N);

    // layer 1: xw1 = x @ W1 ; h = relu(gather(xw1) + b1)
    k_sgemm<HID_C><<<(N + 127) / 128, 256>>>(x, W1, g_xw1, N);
    k_gather<HID_C, true><<<GW, 256>>>(g_xw1, b1, g_acc, N);

    // layer 2: hw2 = h @ W2 ; z = gather(hw2) + b2
    k_sgemm<OUT_C><<<(N + 127) / 128, 256>>>(g_acc, W2, g_hw2, N);
    k_gather<OUT_C, false><<<GW, 256>>>(g_hw2, b2, z, N);

    // Student-t soft assignment
    k_q<<<148 * 8, 256>>>(z, cluster, q, N);
}